// round 13
// baseline (speedup 1.0000x reference)
#include <cuda_runtime.h>
#include <cuda_bf16.h>
#include <math.h>
#include <stdint.h>

#define N 3072
#define F_IN 512
#define NHID 64
#define NHEADS 4
#define NGRAPH 3
#define NCLASS 16
#define ALPHA 0.2f

// ---------------- scratch globals (no allocation) ----------------
__device__ float2 g_E1[NGRAPH * NHEADS * N];                  // {exp(f1), exp(a*f1)}
__device__ __nv_bfloat16 g_E2b[NGRAPH * NHEADS * N];          // bf16(exp(f2))
__device__ __nv_bfloat16 g_E2ab[NGRAPH * NHEADS * N];         // bf16(exp(a*f2))
__device__ __nv_bfloat16 g_WhTh[NGRAPH * NHEADS * NHID * N];  // [gh][o][m] (attn B)
__device__ __nv_bfloat16 g_xh[N * F_IN];                      // x bf16 hi
__device__ __nv_bfloat16 g_WTh[NGRAPH * NHEADS * NHID * F_IN];// W^T [gh][o][f] hi
__device__ __nv_bfloat16 g_WTl[NGRAPH * NHEADS * NHID * F_IN];// W^T lo
__device__ uint32_t g_adjbits[NGRAPH * N * (N / 32)];         // adj bitmask
__device__ float g_hbuf[NGRAPH * N * NHEADS * NHID];          // [g][n][h*64+o]

// ---------------- helpers ----------------
__device__ __forceinline__ uint32_t smem_u32(const void* p) {
    uint32_t a;
    asm("{ .reg .u64 t; cvta.to.shared.u64 t, %1; cvt.u32.u64 %0, t; }" : "=r"(a) : "l"(p));
    return a;
}
__device__ __forceinline__ uint32_t bf16pack(float lo, float hi) {
    uint32_t r;
    asm("cvt.rn.satfinite.bf16x2.f32 %0, %1, %2;" : "=r"(r) : "f"(hi), "f"(lo));
    return r;  // low 16 bits = lo-arg
}
__device__ __forceinline__ void ldsm4(uint32_t* r, uint32_t addr) {
    asm volatile("ldmatrix.sync.aligned.m8n8.x4.shared.b16 {%0,%1,%2,%3}, [%4];"
                 : "=r"(r[0]), "=r"(r[1]), "=r"(r[2]), "=r"(r[3]) : "r"(addr));
}
__device__ __forceinline__ void mma16816(float* c, const uint32_t* a, const uint32_t* b) {
    asm volatile("mma.sync.aligned.m16n8k16.row.col.f32.bf16.bf16.f32 "
                 "{%0,%1,%2,%3}, {%4,%5,%6,%7}, {%8,%9}, {%0,%1,%2,%3};"
                 : "+f"(c[0]), "+f"(c[1]), "+f"(c[2]), "+f"(c[3])
                 : "r"(a[0]), "r"(a[1]), "r"(a[2]), "r"(a[3]), "r"(b[0]), "r"(b[1]));
}
__device__ __forceinline__ uint32_t pmaxmul(uint32_t e1p, uint32_t e1ap, uint32_t u, uint32_t v) {
    uint32_t r;
    asm("{ .reg .b32 t1, t2;\n\t"
        "mul.bf16x2 t1, %1, %3;\n\t"
        "mul.bf16x2 t2, %2, %4;\n\t"
        "max.bf16x2 %0, t1, t2; }"
        : "=r"(r) : "r"(e1p), "r"(e1ap), "r"(u), "r"(v));
    return r;
}
#define SWZ(x) ((x) ^ ((((uint32_t)(x)) >> 3) & 0x70))

// ---------------------------------------------------------------------------
// Prep (merged): blocks [0,1536): x -> bf16 hi. Blocks [1536,1632): W^T split.
// ---------------------------------------------------------------------------
__global__ void prep_kernel(const float* __restrict__ x, const float* __restrict__ W) {
    int bx = blockIdx.x;
    int t = threadIdx.x;
    if (bx < 1536) {
        int idx = bx * 256 + t;
        float4 v = ((const float4*)x)[idx];
        uint32_t h0 = bf16pack(v.x, v.y), h1 = bf16pack(v.z, v.w);
        *(uint2*)&g_xh[(size_t)idx * 4] = make_uint2(h0, h1);
    } else {
        __shared__ float tile[64][65];
        int b2 = bx - 1536;
        int gh = b2 >> 3, f0 = (b2 & 7) * 64;
        const float* Wgh = W + (size_t)gh * F_IN * NHID + (size_t)f0 * NHID;
#pragma unroll
        for (int i = 0; i < 16; i++) {
            int idx = t + 256 * i;
            tile[idx >> 6][idx & 63] = Wgh[idx];
        }
        __syncthreads();
        int o = t >> 2, fq = t & 3;
        size_t base = ((size_t)gh * 64 + o) * F_IN + f0 + fq * 16;
#pragma unroll
        for (int j = 0; j < 8; j++) {
            int f = fq * 16 + 2 * j;
            float w0 = tile[f][o], w1 = tile[f + 1][o];
            uint32_t hv = bf16pack(w0, w1);
            float l0 = w0 - __uint_as_float(hv << 16);
            float l1 = w1 - __uint_as_float(hv & 0xffff0000u);
            *(uint32_t*)&g_WTh[base + 2 * j] = hv;
            *(uint32_t*)&g_WTl[base + 2 * j] = bf16pack(l0, l1);
        }
    }
}

// ---------------------------------------------------------------------------
// Prep: adj -> bitmask via ballot.
// ---------------------------------------------------------------------------
__global__ void adjpack_kernel(const int* __restrict__ adj) {
    int lane = threadIdx.x & 31;
    size_t wid = ((size_t)blockIdx.x * 256 + threadIdx.x) >> 5;
    size_t base = wid * 1024;
    uint32_t myw = 0;
#pragma unroll
    for (int i = 0; i < 32; i++) {
        int v = adj[base + i * 32 + lane];
        uint32_t b = __ballot_sync(0xffffffffu, v > 0);
        if (lane == i) myw = b;
    }
    g_adjbits[base / 32 + lane] = myw;
}

// ---------------------------------------------------------------------------
// Kernel 1: Wh = x@W (mma.sync, 2-term: x_hi*(W_hi+W_lo), double-buffered).
// Epilogue: WhT bf16 + f1/f2 -> E1/E2.
// ---------------------------------------------------------------------------
#define WH_BUF 32768
#define WH_SMEM 66048
extern __shared__ char whsm[];
__global__ __launch_bounds__(256, 2) void wh_mma_kernel(const float* __restrict__ a) {
    char* sm = whsm;
    uint32_t smb = smem_u32(sm);
    float* a_s = (float*)(sm + 65536);
    int t = threadIdx.x;
    int wid = t >> 5, lane = t & 31;
    int gh = blockIdx.y;
    int n0 = blockIdx.x * 128;

    if (t < 128) a_s[t] = a[gh * 128 + t];

    int lrow = lane & 7, seg = lane >> 3;
    int arow = wid * 16 + lrow + (seg & 1) * 8;
    uint32_t a_sel = (uint32_t)((seg >> 1) * 16);
    int bnb = lrow + (seg >> 1) * 8;
    uint32_t b_sel = (uint32_t)((seg & 1) * 16);

    int rowA = t >> 1, halfA = t & 1;
    int ob = t >> 2, qb = t & 3;

    float acc[32];
#pragma unroll
    for (int i = 0; i < 32; i++) acc[i] = 0.f;

    auto stage = [&](int f0, int b) {
        uint32_t bb = (uint32_t)b * WH_BUF;
        const uint4* sh = (const uint4*)&g_xh[(size_t)(n0 + rowA) * F_IN + f0 + halfA * 32];
#pragma unroll
        for (int j = 0; j < 4; j++) {
            uint32_t s = SWZ((uint32_t)(rowA * 128 + halfA * 64 + j * 16)) + bb;
            *(uint4*)(sm + s) = sh[j];
        }
        const uint4* th = (const uint4*)&g_WTh[((size_t)gh * 64 + ob) * F_IN + f0 + qb * 16];
        const uint4* tl = (const uint4*)&g_WTl[((size_t)gh * 64 + ob) * F_IN + f0 + qb * 16];
#pragma unroll
        for (int j = 0; j < 2; j++) {
            uint32_t s = SWZ((uint32_t)(ob * 128 + qb * 32 + j * 16)) + bb;
            *(uint4*)(sm + 16384 + s) = th[j];
            *(uint4*)(sm + 24576 + s) = tl[j];
        }
    };

    stage(0, 0);
    __syncthreads();
    for (int ci = 0; ci < 8; ci++) {
        int b = ci & 1;
        if (ci < 7) stage((ci + 1) * 64, b ^ 1);
        uint32_t bb = (uint32_t)b * WH_BUF;
#pragma unroll
        for (int ks = 0; ks < 4; ks++) {
            uint32_t ao = SWZ((uint32_t)(arow * 128 + ks * 32) + a_sel) + bb;
            uint32_t ah[4];
            ldsm4(ah, smb + ao);
#pragma unroll
            for (int ng = 0; ng < 4; ng++) {
                uint32_t bo = SWZ((uint32_t)((ng * 16 + bnb) * 128 + ks * 32) + b_sel) + bb;
                uint32_t bh[4], bl[4];
                ldsm4(bh, smb + 16384 + bo);
                ldsm4(bl, smb + 24576 + bo);
                mma16816(acc + ng * 8, ah, bh);
                mma16816(acc + ng * 8 + 4, ah, bh + 2);
                mma16816(acc + ng * 8, ah, bl);
                mma16816(acc + ng * 8 + 4, ah, bl + 2);
            }
        }
        __syncthreads();
    }

    int gID = lane >> 2, tig = lane & 3;
    int rA = wid * 16 + gID, rB = rA + 8;
    float* ftile = (float*)sm;  // [128][66]
#pragma unroll
    for (int ng = 0; ng < 4; ng++) {
        int col = ng * 16 + 2 * tig;
        ftile[rA * 66 + col] = acc[ng * 8 + 0];
        ftile[rA * 66 + col + 1] = acc[ng * 8 + 1];
        ftile[rB * 66 + col] = acc[ng * 8 + 2];
        ftile[rB * 66 + col + 1] = acc[ng * 8 + 3];
        ftile[rA * 66 + col + 8] = acc[ng * 8 + 4];
        ftile[rA * 66 + col + 9] = acc[ng * 8 + 5];
        ftile[rB * 66 + col + 8] = acc[ng * 8 + 6];
        ftile[rB * 66 + col + 9] = acc[ng * 8 + 7];
    }
    __syncthreads();
    {
        int o = t >> 2, rq = t & 3;
        size_t base = ((size_t)gh * 64 + o) * N + n0 + rq * 32;
#pragma unroll
        for (int j = 0; j < 16; j++) {
            int r = rq * 32 + 2 * j;
            *(uint32_t*)&g_WhTh[base + 2 * j] = bf16pack(ftile[r * 66 + o], ftile[(r + 1) * 66 + o]);
        }
    }
    {
        int row = t >> 1, halfo = t & 1;
        const float* fr = ftile + row * 66 + halfo * 32;
        const float* a1 = a_s + halfo * 32;
        const float* a2 = a_s + 64 + halfo * 32;
        float s1 = 0.f, s2 = 0.f;
#pragma unroll 8
        for (int o = 0; o < 32; o++) {
            float w = fr[o];
            s1 = fmaf(w, a1[o], s1);
            s2 = fmaf(w, a2[o], s2);
        }
        s1 += __shfl_xor_sync(0xffffffffu, s1, 1);
        s2 += __shfl_xor_sync(0xffffffffu, s2, 1);
        if (halfo == 0) {
            int n = n0 + row;
            g_E1[gh * N + n] = make_float2(__expf(s1), __expf(ALPHA * s1));
            g_E2b[gh * N + n] = __float2bfloat16(__expf(s2));
            g_E2ab[gh * N + n] = __float2bfloat16(__expf(ALPHA * s2));
        }
    }
}

// ---------------------------------------------------------------------------
// Kernel 2: attention. Register-direct A (P), 32 rows/warp, B-ldsm shared
// across two 16-row A-tiles. Block = 128 threads = 4 warps = 128 queries.
// grid (24, 12), 2 CTAs/SM: independent barriers de-phase P-build vs MMA.
// ---------------------------------------------------------------------------
#define SM_B(b)   ((b) * 16384)
#define SM_E2(b)  (32768 + (b) * 1024)
#define SM_E2A(b) (32768 + (b) * 1024 + 256)
#define ATTN_SMEM 34816
extern __shared__ char attn_sm[];
__global__ __launch_bounds__(128, 2) void attn_mma_kernel() {
    char* sm = attn_sm;
    uint32_t smb = smem_u32(sm);
    int t = threadIdx.x;
    int wid = t >> 5, lane = t & 31;
    int gh = blockIdx.y, gg = gh >> 2, h = gh & 3;
    int n0 = blockIdx.x * 128;
    int g = lane >> 2, tig = lane & 3;

    uint32_t e1p[4], e1ap[4];
#pragma unroll
    for (int i = 0; i < 4; i++) {
        float2 E1v = g_E1[gh * N + n0 + wid * 32 + i * 8 + g];
        e1p[i] = bf16pack(E1v.x, E1v.x);
        e1ap[i] = bf16pack(E1v.y, E1v.y);
    }
    const uint4* bits0 = (const uint4*)(g_adjbits + ((size_t)gg * N + n0 + wid * 32 + g) * 96);
    const uint4* bits1 = (const uint4*)(g_adjbits + ((size_t)gg * N + n0 + wid * 32 + 8 + g) * 96);
    const uint4* bits2 = (const uint4*)(g_adjbits + ((size_t)gg * N + n0 + wid * 32 + 16 + g) * 96);
    const uint4* bits3 = (const uint4*)(g_adjbits + ((size_t)gg * N + n0 + wid * 32 + 24 + g) * 96);

    // staging ids: 128 threads, each covers (ob, mq2) and (ob, mq2+1)
    int ob = t >> 1, mq2 = (t & 1) * 2;
    const __nv_bfloat16* bh_row = g_WhTh + ((size_t)gh * 64 + ob) * N;
    const uint2* e2src = (const uint2*)(g_E2b + (size_t)gh * N);
    const uint2* e2asrc = (const uint2*)(g_E2ab + (size_t)gh * N);

    int lrow = lane & 7, seg = lane >> 3;
    int bnb = lrow + (seg >> 1) * 8;
    uint32_t b_sel = (uint32_t)((seg & 1) * 16);

    const uint32_t ones2[2] = {0x3F803F80u, 0x3F803F80u};
    float acc[64], accs[8];
#pragma unroll
    for (int i = 0; i < 64; i++) acc[i] = 0.f;
#pragma unroll
    for (int i = 0; i < 8; i++) accs[i] = 0.f;

    auto stage = [&](int c, int b) {
#pragma unroll
        for (int mi = 0; mi < 2; mi++) {
            int mq = mq2 + mi;
            uint32_t b_off = (uint32_t)((mq >> 1) * 8192 + ob * 128 + (mq & 1) * 64);
            const uint4* hs = (const uint4*)(bh_row + c * 128 + mq * 32);
#pragma unroll
            for (int jj = 0; jj < 4; jj++)
                *(uint4*)(sm + SM_B(b) + SWZ(b_off + jj * 16)) = hs[jj];
        }
        if (t < 32) ((uint2*)(sm + SM_E2(b)))[t] = e2src[c * 32 + t];
        else if (t < 64) ((uint2*)(sm + SM_E2A(b)))[t - 32] = e2asrc[c * 32 + (t - 32)];
    };

    stage(0, 0);
    __syncthreads();
    for (int c = 0; c < 24; c++) {
        int b = c & 1;
        if (c < 23) stage(c + 1, b ^ 1);
        uint4 w0 = bits0[c];
        uint4 w1 = bits1[c];
        uint4 w2 = bits2[c];
        uint4 w3 = bits3[c];
        const uint32_t* e2s = (const uint32_t*)(sm + SM_E2(b));
        const uint32_t* e2as = (const uint32_t*)(sm + SM_E2A(b));
#pragma unroll
        for (int ks = 0; ks < 8; ks++) {
            uint32_t ul = e2s[ks * 8 + tig], uh = e2s[ks * 8 + 4 + tig];
            uint32_t vl = e2as[ks * 8 + tig], vh = e2as[ks * 8 + 4 + tig];
            uint32_t mb0 = ((const uint32_t*)&w0)[ks >> 1] >> ((ks & 1) * 16);
            uint32_t mb1 = ((const uint32_t*)&w1)[ks >> 1] >> ((ks & 1) * 16);
            uint32_t mb2 = ((const uint32_t*)&w2)[ks >> 1] >> ((ks & 1) * 16);
            uint32_t mb3 = ((const uint32_t*)&w3)[ks >> 1] >> ((ks & 1) * 16);
            uint32_t afA[4], afB[4];
            {
                uint32_t b00 = (mb0 >> (2 * tig)) & 3u;
                uint32_t b01 = (mb0 >> (2 * tig + 8)) & 3u;
                uint32_t b10 = (mb1 >> (2 * tig)) & 3u;
                uint32_t b11 = (mb1 >> (2 * tig + 8)) & 3u;
                afA[0] = pmaxmul(e1p[0], e1ap[0], ul, vl) & ((b00 & 1u) * 0xffffu + (b00 & 2u) * 0x7fff8000u);
                afA[1] = pmaxmul(e1p[1], e1ap[1], ul, vl) & ((b10 & 1u) * 0xffffu + (b10 & 2u) * 0x7fff8000u);
                afA[2] = pmaxmul(e1p[0], e1ap[0], uh, vh) & ((b01 & 1u) * 0xffffu + (b01 & 2u) * 0x7fff8000u);
                afA[3] = pmaxmul(e1p[1], e1ap[1], uh, vh) & ((b11 & 1u) * 0xffffu + (b11 & 2u) * 0x7fff8000u);
            }
            {
                uint32_t b00 = (mb2 >> (2 * tig)) & 3u;
                uint32_t b01 = (mb2 >> (2 * tig + 8)) & 3u;
                uint32_t b10 = (mb3 >> (2 * tig)) & 3u;
                uint32_t b11 = (mb3 >> (2 * tig + 8)) & 3u;
                afB[0] = pmaxmul(e1p[2], e1ap[2], ul, vl) & ((b00 & 1u) * 0xffffu + (b00 & 2u) * 0x7fff8000u);
                afB[1] = pmaxmul(e1p[3], e1ap[3], ul, vl) & ((b10 & 1u) * 0xffffu + (b10 & 2u) * 0x7fff8000u);
                afB[2] = pmaxmul(e1p[2], e1ap[2], uh, vh) & ((b01 & 1u) * 0xffffu + (b01 & 2u) * 0x7fff8000u);
                afB[3] = pmaxmul(e1p[3], e1ap[3], uh, vh) & ((b11 & 1u) * 0xffffu + (b11 & 2u) * 0x7fff8000u);
            }
            mma16816(accs, afA, ones2);
            mma16816(accs + 4, afB, ones2);
            uint32_t bk = (uint32_t)((ks >> 2) * 8192 + (ks & 3) * 32) + b_sel;
#pragma unroll
            for (int ng = 0; ng < 4; ng++) {
                uint32_t bo = SWZ(bk + (uint32_t)((ng * 16 + bnb) * 128));
                uint32_t bhf[4];
                ldsm4(bhf, smb + SM_B(b) + bo);
                mma16816(acc + ng * 8, afA, bhf);
                mma16816(acc + ng * 8 + 4, afA, bhf + 2);
                mma16816(acc + 32 + ng * 8, afB, bhf);
                mma16816(acc + 32 + ng * 8 + 4, afB, bhf + 2);
            }
        }
        __syncthreads();
    }

#pragma unroll
    for (int ti = 0; ti < 2; ti++) {
        int rA = wid * 32 + ti * 16 + g, rB = rA + 8;
        float invA = 1.f / accs[ti * 4 + 0];
        float invB = 1.f / accs[ti * 4 + 2];
        float* outA = &g_hbuf[((size_t)gg * N + n0 + rA) * 256 + h * 64];
        float* outB = &g_hbuf[((size_t)gg * N + n0 + rB) * 256 + h * 64];
#pragma unroll
        for (int nt = 0; nt < 8; nt++) {
            int col = nt * 8 + 2 * tig;
            float v0 = acc[ti * 32 + nt * 4 + 0] * invA;
            float v1 = acc[ti * 32 + nt * 4 + 1] * invA;
            float v2 = acc[ti * 32 + nt * 4 + 2] * invB;
            float v3 = acc[ti * 32 + nt * 4 + 3] * invB;
            v0 = v0 > 0.f ? v0 : expm1f(v0);
            v1 = v1 > 0.f ? v1 : expm1f(v1);
            v2 = v2 > 0.f ? v2 : expm1f(v2);
            v3 = v3 > 0.f ? v3 : expm1f(v3);
            *(float2*)(outA + col) = make_float2(v0, v1);
            *(float2*)(outB + col) = make_float2(v2, v3);
        }
    }
}

// ---------------------------------------------------------------------------
// Kernel 3: head. 8 nodes/block, 256 threads, d-split pairs.
// ---------------------------------------------------------------------------
__global__ void head_kernel(const float* __restrict__ W_int, const float* __restrict__ b_int,
                            const float* __restrict__ W_fus, const float* __restrict__ b_fus,
                            float* __restrict__ out) {
    __shared__ float hs[8][776];
    __shared__ float wint_s[16][260];
    __shared__ float wfus_s[16][49];
    __shared__ float xis[8][49];
    int n0 = blockIdx.x * 8;
    int t = threadIdx.x;

    for (int i = t; i < NCLASS * 64; i += 256) {
        int c = i >> 6, dq = i & 63;
        *(float4*)&wint_s[c][dq * 4] = ((const float4*)W_int)[i];
    }
    for (int i = t; i < NCLASS * 48; i += 256) wfus_s[i / 48][i % 48] = W_fus[i];
    for (int i = t; i < 8 * 192; i += 256) {
        int nl = i / 192, rq = i % 192;
        int d4 = rq * 4, g = d4 >> 8, dd = d4 & 255;
        *(float4*)&hs[nl][d4] = *(const float4*)&g_hbuf[((size_t)g * N + n0 + nl) * 256 + dd];
    }
    __syncthreads();

    int c = t & 15, halfd = (t >> 4) & 1, nl = t >> 5;
    {
        const float4* wr = (const float4*)&wint_s[c][0];
#pragma unroll
        for (int g = 0; g < NGRAPH; g++) {
            float a0 = 0.f, a1 = 0.f, a2 = 0.f, a3 = 0.f;
            const float4* hr = (const float4*)&hs[nl][g * 256];
#pragma unroll 8
            for (int d = halfd * 32; d < halfd * 32 + 32; d++) {
                float4 hv = hr[d], wv = wr[d];
                a0 = fmaf(hv.x, wv.x, a0);
                a1 = fmaf(hv.y, wv.y, a1);
                a2 = fmaf(hv.z, wv.z, a2);
                a3 = fmaf(hv.w, wv.w, a3);
            }
            float acc = (a0 + a1) + (a2 + a3);
            acc += __shfl_xor_sync(0xffffffffu, acc, 16);
            if (halfd == 0) {
                acc += b_int[c];
                xis[nl][g * 16 + c] = acc > 0.f ? acc : expm1f(acc);
            }
        }
    }
    __syncthreads();
    if (halfd == 0) {
        float acc = b_fus[c];
        const float* wr = wfus_s[c];
        const float* xr = xis[nl];
#pragma unroll
        for (int j = 0; j < 48; j++) acc = fmaf(xr[j], wr[j], acc);
        float mx = acc;
#pragma unroll
        for (int k = 8; k; k >>= 1) mx = fmaxf(mx, __shfl_xor_sync(0xffffffffu, mx, k, 16));
        float s = expf(acc - mx);
#pragma unroll
        for (int k = 8; k; k >>= 1) s += __shfl_xor_sync(0xffffffffu, s, k, 16);
        out[(size_t)(n0 + nl) * NCLASS + c] = acc - mx - logf(s);
    }
}

// ---------------------------------------------------------------------------
// Kernel 4: l1_loss = mean(|W_fus|)
// ---------------------------------------------------------------------------
__global__ void l1_kernel(const float* __restrict__ W_fus, float* __restrict__ out) {
    __shared__ float red[256];
    int t = threadIdx.x;
    float s = 0.f;
    for (int i = t; i < NCLASS * NGRAPH * NCLASS; i += 256) s += fabsf(W_fus[i]);
    red[t] = s;
    __syncthreads();
    for (int k = 128; k; k >>= 1) {
        if (t < k) red[t] += red[t + k];
        __syncthreads();
    }
    if (t == 0) out[(size_t)N * NCLASS] = red[0] / (float)(NCLASS * NGRAPH * NCLASS);
}

// ---------------------------------------------------------------------------
extern "C" void kernel_launch(void* const* d_in, const int* in_sizes, int n_in,
                              void* d_out, int out_size) {
    const float* x     = (const float*)d_in[0];
    const int*   adj   = (const int*)d_in[1];
    const float* W     = (const float*)d_in[2];
    const float* a     = (const float*)d_in[3];
    const float* W_int = (const float*)d_in[4];
    const float* b_int = (const float*)d_in[5];
    const float* W_fus = (const float*)d_in[6];
    const float* b_fus = (const float*)d_in[7];
    float* out = (float*)d_out;

    cudaFuncSetAttribute(wh_mma_kernel, cudaFuncAttributeMaxDynamicSharedMemorySize, WH_SMEM);
    cudaFuncSetAttribute(attn_mma_kernel, cudaFuncAttributeMaxDynamicSharedMemorySize, ATTN_SMEM);

    // Fork: adjpack (+l1) on a side stream, overlapped with prep+wh_mma.
    // Streams/events created per call and intentionally leaked (few calls ever;
    // replays reuse the captured graph).
    cudaStream_t s2;
    cudaStreamCreateWithFlags(&s2, cudaStreamNonBlocking);
    cudaEvent_t evF, evJ;
    cudaEventCreateWithFlags(&evF, cudaEventDisableTiming);
    cudaEventCreateWithFlags(&evJ, cudaEventDisableTiming);

    cudaEventRecord(evF, 0);
    cudaStreamWaitEvent(s2, evF, 0);
    adjpack_kernel<<<(NGRAPH * N * N) / (8 * 1024), 256, 0, s2>>>(adj);
    if (out_size > N * NCLASS) l1_kernel<<<1, 256, 0, s2>>>(W_fus, out);

    prep_kernel<<<1632, 256>>>(x, W);
    wh_mma_kernel<<<dim3(N / 128, NGRAPH * NHEADS), 256, WH_SMEM>>>(a);

    cudaEventRecord(evJ, s2);
    cudaStreamWaitEvent(0, evJ, 0);
    attn_mma_kernel<<<dim3(N / 128, NGRAPH * NHEADS), 128, ATTN_SMEM>>>();
    head_kernel<<<N / 8, 256>>>(W_int, b_int, W_fus, b_fus, out);
}

// round 14
// speedup vs baseline: 1.1643x; 1.1643x over previous
#include <cuda_runtime.h>
#include <cuda_bf16.h>
#include <math.h>
#include <stdint.h>

#define N 3072
#define F_IN 512
#define NHID 64
#define NHEADS 4
#define NGRAPH 3
#define NCLASS 16
#define ALPHA 0.2f

// ---------------- scratch globals (no allocation) ----------------
__device__ float2 g_E1[NGRAPH * NHEADS * N];                  // {exp(f1), exp(a*f1)}
__device__ __nv_bfloat16 g_E2b[NGRAPH * NHEADS * N];          // bf16(exp(f2))
__device__ __nv_bfloat16 g_E2ab[NGRAPH * NHEADS * N];         // bf16(exp(a*f2))
__device__ __nv_bfloat16 g_WhTh[NGRAPH * NHEADS * NHID * N];  // [gh][o][m] (attn B)
__device__ __nv_bfloat16 g_xh[N * F_IN];                      // x bf16 hi
__device__ __nv_bfloat16 g_WTh[NGRAPH * NHEADS * NHID * F_IN];// W^T [gh][o][f] hi
__device__ __nv_bfloat16 g_WTl[NGRAPH * NHEADS * NHID * F_IN];// W^T lo
__device__ uint32_t g_adjbits[NGRAPH * N * (N / 32)];         // adj bitmask
__device__ float g_hbuf[NGRAPH * N * NHEADS * NHID];          // [g][n][h*64+o]

// ---------------- helpers ----------------
__device__ __forceinline__ uint32_t smem_u32(const void* p) {
    uint32_t a;
    asm("{ .reg .u64 t; cvta.to.shared.u64 t, %1; cvt.u32.u64 %0, t; }" : "=r"(a) : "l"(p));
    return a;
}
__device__ __forceinline__ uint32_t bf16pack(float lo, float hi) {
    uint32_t r;
    asm("cvt.rn.satfinite.bf16x2.f32 %0, %1, %2;" : "=r"(r) : "f"(hi), "f"(lo));
    return r;  // low 16 bits = lo-arg
}
__device__ __forceinline__ void ldsm4(uint32_t* r, uint32_t addr) {
    asm volatile("ldmatrix.sync.aligned.m8n8.x4.shared.b16 {%0,%1,%2,%3}, [%4];"
                 : "=r"(r[0]), "=r"(r[1]), "=r"(r[2]), "=r"(r[3]) : "r"(addr));
}
__device__ __forceinline__ void mma16816(float* c, const uint32_t* a, const uint32_t* b) {
    asm volatile("mma.sync.aligned.m16n8k16.row.col.f32.bf16.bf16.f32 "
                 "{%0,%1,%2,%3}, {%4,%5,%6,%7}, {%8,%9}, {%0,%1,%2,%3};"
                 : "+f"(c[0]), "+f"(c[1]), "+f"(c[2]), "+f"(c[3])
                 : "r"(a[0]), "r"(a[1]), "r"(a[2]), "r"(a[3]), "r"(b[0]), "r"(b[1]));
}
__device__ __forceinline__ uint32_t pmaxmul(uint32_t e1p, uint32_t e1ap, uint32_t u, uint32_t v) {
    uint32_t r;
    asm("{ .reg .b32 t1, t2;\n\t"
        "mul.bf16x2 t1, %1, %3;\n\t"
        "mul.bf16x2 t2, %2, %4;\n\t"
        "max.bf16x2 %0, t1, t2; }"
        : "=r"(r) : "r"(e1p), "r"(e1ap), "r"(u), "r"(v));
    return r;
}
__device__ __forceinline__ void cpasync16(uint32_t saddr, const void* gptr) {
    asm volatile("cp.async.cg.shared.global [%0], [%1], 16;" :: "r"(saddr), "l"(gptr) : "memory");
}
__device__ __forceinline__ void cpasync8(uint32_t saddr, const void* gptr) {
    asm volatile("cp.async.ca.shared.global [%0], [%1], 8;" :: "r"(saddr), "l"(gptr) : "memory");
}
#define CP_COMMIT() asm volatile("cp.async.commit_group;" ::: "memory")
#define CP_WAIT0()  asm volatile("cp.async.wait_group 0;" ::: "memory")
#define SWZ(x) ((x) ^ ((((uint32_t)(x)) >> 3) & 0x70))

// ---------------------------------------------------------------------------
// Prep (merged): blocks [0,1536): x -> bf16 hi. Blocks [1536,1632): W^T split.
// ---------------------------------------------------------------------------
__global__ void prep_kernel(const float* __restrict__ x, const float* __restrict__ W) {
    int bx = blockIdx.x;
    int t = threadIdx.x;
    if (bx < 1536) {
        int idx = bx * 256 + t;
        float4 v = ((const float4*)x)[idx];
        uint32_t h0 = bf16pack(v.x, v.y), h1 = bf16pack(v.z, v.w);
        *(uint2*)&g_xh[(size_t)idx * 4] = make_uint2(h0, h1);
    } else {
        __shared__ float tile[64][65];
        int b2 = bx - 1536;
        int gh = b2 >> 3, f0 = (b2 & 7) * 64;
        const float* Wgh = W + (size_t)gh * F_IN * NHID + (size_t)f0 * NHID;
#pragma unroll
        for (int i = 0; i < 16; i++) {
            int idx = t + 256 * i;
            tile[idx >> 6][idx & 63] = Wgh[idx];
        }
        __syncthreads();
        int o = t >> 2, fq = t & 3;
        size_t base = ((size_t)gh * 64 + o) * F_IN + f0 + fq * 16;
#pragma unroll
        for (int j = 0; j < 8; j++) {
            int f = fq * 16 + 2 * j;
            float w0 = tile[f][o], w1 = tile[f + 1][o];
            uint32_t hv = bf16pack(w0, w1);
            float l0 = w0 - __uint_as_float(hv << 16);
            float l1 = w1 - __uint_as_float(hv & 0xffff0000u);
            *(uint32_t*)&g_WTh[base + 2 * j] = hv;
            *(uint32_t*)&g_WTl[base + 2 * j] = bf16pack(l0, l1);
        }
    }
}

// ---------------------------------------------------------------------------
// Prep: adj -> bitmask via ballot.
// ---------------------------------------------------------------------------
__global__ void adjpack_kernel(const int* __restrict__ adj) {
    int lane = threadIdx.x & 31;
    size_t wid = ((size_t)blockIdx.x * 256 + threadIdx.x) >> 5;
    size_t base = wid * 1024;
    uint32_t myw = 0;
#pragma unroll
    for (int i = 0; i < 32; i++) {
        int v = adj[base + i * 32 + lane];
        uint32_t b = __ballot_sync(0xffffffffu, v > 0);
        if (lane == i) myw = b;
    }
    g_adjbits[base / 32 + lane] = myw;
}

// ---------------------------------------------------------------------------
// Kernel 1: Wh = x@W (mma.sync, 2-term, double-buffered cp.async pipeline).
// Epilogue: WhT bf16 + f1/f2 -> E1/E2.
// ---------------------------------------------------------------------------
#define WH_BUF 32768
#define WH_SMEM 66048
extern __shared__ char whsm[];
__global__ __launch_bounds__(256, 2) void wh_mma_kernel(const float* __restrict__ a) {
    char* sm = whsm;
    uint32_t smb = smem_u32(sm);
    float* a_s = (float*)(sm + 65536);
    int t = threadIdx.x;
    int wid = t >> 5, lane = t & 31;
    int gh = blockIdx.y;
    int n0 = blockIdx.x * 128;

    if (t < 128) a_s[t] = a[gh * 128 + t];

    int lrow = lane & 7, seg = lane >> 3;
    int arow = wid * 16 + lrow + (seg & 1) * 8;
    uint32_t a_sel = (uint32_t)((seg >> 1) * 16);
    int bnb = lrow + (seg >> 1) * 8;
    uint32_t b_sel = (uint32_t)((seg & 1) * 16);

    int rowA = t >> 1, halfA = t & 1;
    int ob = t >> 2, qb = t & 3;

    float acc[32];
#pragma unroll
    for (int i = 0; i < 32; i++) acc[i] = 0.f;

    auto stage = [&](int f0, int b) {
        uint32_t bb = (uint32_t)b * WH_BUF;
        const char* sh = (const char*)&g_xh[(size_t)(n0 + rowA) * F_IN + f0 + halfA * 32];
#pragma unroll
        for (int j = 0; j < 4; j++) {
            uint32_t s = SWZ((uint32_t)(rowA * 128 + halfA * 64 + j * 16)) + bb;
            cpasync16(smb + s, sh + j * 16);
        }
        const char* th = (const char*)&g_WTh[((size_t)gh * 64 + ob) * F_IN + f0 + qb * 16];
        const char* tl = (const char*)&g_WTl[((size_t)gh * 64 + ob) * F_IN + f0 + qb * 16];
#pragma unroll
        for (int j = 0; j < 2; j++) {
            uint32_t s = SWZ((uint32_t)(ob * 128 + qb * 32 + j * 16)) + bb;
            cpasync16(smb + 16384 + s, th + j * 16);
            cpasync16(smb + 24576 + s, tl + j * 16);
        }
    };

    stage(0, 0);
    CP_COMMIT();
    CP_WAIT0();
    __syncthreads();
    for (int ci = 0; ci < 8; ci++) {
        int b = ci & 1;
        if (ci < 7) { stage((ci + 1) * 64, b ^ 1); CP_COMMIT(); }
        uint32_t bb = (uint32_t)b * WH_BUF;
#pragma unroll
        for (int ks = 0; ks < 4; ks++) {
            uint32_t ao = SWZ((uint32_t)(arow * 128 + ks * 32) + a_sel) + bb;
            uint32_t ah[4];
            ldsm4(ah, smb + ao);
#pragma unroll
            for (int ng = 0; ng < 4; ng++) {
                uint32_t bo = SWZ((uint32_t)((ng * 16 + bnb) * 128 + ks * 32) + b_sel) + bb;
                uint32_t bh[4], bl[4];
                ldsm4(bh, smb + 16384 + bo);
                ldsm4(bl, smb + 24576 + bo);
                mma16816(acc + ng * 8, ah, bh);
                mma16816(acc + ng * 8 + 4, ah, bh + 2);
                mma16816(acc + ng * 8, ah, bl);
                mma16816(acc + ng * 8 + 4, ah, bl + 2);
            }
        }
        CP_WAIT0();
        __syncthreads();
    }

    int gID = lane >> 2, tig = lane & 3;
    int rA = wid * 16 + gID, rB = rA + 8;
    float* ftile = (float*)sm;  // [128][66]
#pragma unroll
    for (int ng = 0; ng < 4; ng++) {
        int col = ng * 16 + 2 * tig;
        ftile[rA * 66 + col] = acc[ng * 8 + 0];
        ftile[rA * 66 + col + 1] = acc[ng * 8 + 1];
        ftile[rB * 66 + col] = acc[ng * 8 + 2];
        ftile[rB * 66 + col + 1] = acc[ng * 8 + 3];
        ftile[rA * 66 + col + 8] = acc[ng * 8 + 4];
        ftile[rA * 66 + col + 9] = acc[ng * 8 + 5];
        ftile[rB * 66 + col + 8] = acc[ng * 8 + 6];
        ftile[rB * 66 + col + 9] = acc[ng * 8 + 7];
    }
    __syncthreads();
    {
        int o = t >> 2, rq = t & 3;
        size_t base = ((size_t)gh * 64 + o) * N + n0 + rq * 32;
#pragma unroll
        for (int j = 0; j < 16; j++) {
            int r = rq * 32 + 2 * j;
            *(uint32_t*)&g_WhTh[base + 2 * j] = bf16pack(ftile[r * 66 + o], ftile[(r + 1) * 66 + o]);
        }
    }
    {
        int row = t >> 1, halfo = t & 1;
        const float* fr = ftile + row * 66 + halfo * 32;
        const float* a1 = a_s + halfo * 32;
        const float* a2 = a_s + 64 + halfo * 32;
        float s1 = 0.f, s2 = 0.f;
#pragma unroll 8
        for (int o = 0; o < 32; o++) {
            float w = fr[o];
            s1 = fmaf(w, a1[o], s1);
            s2 = fmaf(w, a2[o], s2);
        }
        s1 += __shfl_xor_sync(0xffffffffu, s1, 1);
        s2 += __shfl_xor_sync(0xffffffffu, s2, 1);
        if (halfo == 0) {
            int n = n0 + row;
            g_E1[gh * N + n] = make_float2(__expf(s1), __expf(ALPHA * s1));
            g_E2b[gh * N + n] = __float2bfloat16(__expf(s2));
            g_E2ab[gh * N + n] = __float2bfloat16(__expf(ALPHA * s2));
        }
    }
}

// ---------------------------------------------------------------------------
// Kernel 2: attention (round-10 proven config + cp.async staging).
// Register-direct A (P), 32 rows/warp, B-ldsm shared across two 16-row
// A-tiles. Block = 256 queries, grid (12, 12).
// ---------------------------------------------------------------------------
#define SM_B(b)   ((b) * 16384)
#define SM_E2(b)  (32768 + (b) * 1024)
#define SM_E2A(b) (32768 + (b) * 1024 + 256)
#define ATTN_SMEM 34816
extern __shared__ char attn_sm[];
__global__ __launch_bounds__(256, 1) void attn_mma_kernel() {
    char* sm = attn_sm;
    uint32_t smb = smem_u32(sm);
    int t = threadIdx.x;
    int wid = t >> 5, lane = t & 31;
    int gh = blockIdx.y, gg = gh >> 2, h = gh & 3;
    int n0 = blockIdx.x * 256;
    int g = lane >> 2, tig = lane & 3;

    uint32_t e1p[4], e1ap[4];
#pragma unroll
    for (int i = 0; i < 4; i++) {
        float2 E1v = g_E1[gh * N + n0 + wid * 32 + i * 8 + g];
        e1p[i] = bf16pack(E1v.x, E1v.x);
        e1ap[i] = bf16pack(E1v.y, E1v.y);
    }
    const uint4* bits0 = (const uint4*)(g_adjbits + ((size_t)gg * N + n0 + wid * 32 + g) * 96);
    const uint4* bits1 = (const uint4*)(g_adjbits + ((size_t)gg * N + n0 + wid * 32 + 8 + g) * 96);
    const uint4* bits2 = (const uint4*)(g_adjbits + ((size_t)gg * N + n0 + wid * 32 + 16 + g) * 96);
    const uint4* bits3 = (const uint4*)(g_adjbits + ((size_t)gg * N + n0 + wid * 32 + 24 + g) * 96);

    int ob = t >> 2, mq = t & 3;
    const __nv_bfloat16* bh_row = g_WhTh + ((size_t)gh * 64 + ob) * N + mq * 32;
    uint32_t b_off_base = (uint32_t)((mq >> 1) * 8192 + ob * 128 + (mq & 1) * 64);
    const uint2* e2src = (const uint2*)(g_E2b + (size_t)gh * N);
    const uint2* e2asrc = (const uint2*)(g_E2ab + (size_t)gh * N);

    int lrow = lane & 7, seg = lane >> 3;
    int bnb = lrow + (seg >> 1) * 8;
    uint32_t b_sel = (uint32_t)((seg & 1) * 16);

    const uint32_t ones2[2] = {0x3F803F80u, 0x3F803F80u};
    float acc[64], accs[8];
#pragma unroll
    for (int i = 0; i < 64; i++) acc[i] = 0.f;
#pragma unroll
    for (int i = 0; i < 8; i++) accs[i] = 0.f;

    auto stage = [&](int c, int b) {
        const char* hs = (const char*)(bh_row + c * 128);
#pragma unroll
        for (int jj = 0; jj < 4; jj++)
            cpasync16(smb + SM_B(b) + SWZ(b_off_base + jj * 16), hs + jj * 16);
        if (t < 32) cpasync8(smb + SM_E2(b) + t * 8, (const char*)(e2src + c * 32 + t));
        else if (t < 64) cpasync8(smb + SM_E2A(b) + (t - 32) * 8, (const char*)(e2asrc + c * 32 + (t - 32)));
    };

    stage(0, 0);
    CP_COMMIT();
    CP_WAIT0();
    __syncthreads();
    for (int c = 0; c < 24; c++) {
        int b = c & 1;
        if (c < 23) { stage(c + 1, b ^ 1); CP_COMMIT(); }
        uint4 w0 = bits0[c];
        uint4 w1 = bits1[c];
        uint4 w2 = bits2[c];
        uint4 w3 = bits3[c];
        const uint32_t* e2s = (const uint32_t*)(sm + SM_E2(b));
        const uint32_t* e2as = (const uint32_t*)(sm + SM_E2A(b));
#pragma unroll
        for (int ks = 0; ks < 8; ks++) {
            uint32_t ul = e2s[ks * 8 + tig], uh = e2s[ks * 8 + 4 + tig];
            uint32_t vl = e2as[ks * 8 + tig], vh = e2as[ks * 8 + 4 + tig];
            uint32_t mb0 = ((const uint32_t*)&w0)[ks >> 1] >> ((ks & 1) * 16);
            uint32_t mb1 = ((const uint32_t*)&w1)[ks >> 1] >> ((ks & 1) * 16);
            uint32_t mb2 = ((const uint32_t*)&w2)[ks >> 1] >> ((ks & 1) * 16);
            uint32_t mb3 = ((const uint32_t*)&w3)[ks >> 1] >> ((ks & 1) * 16);
            uint32_t afA[4], afB[4];
            {
                uint32_t b00 = (mb0 >> (2 * tig)) & 3u;
                uint32_t b01 = (mb0 >> (2 * tig + 8)) & 3u;
                uint32_t b10 = (mb1 >> (2 * tig)) & 3u;
                uint32_t b11 = (mb1 >> (2 * tig + 8)) & 3u;
                afA[0] = pmaxmul(e1p[0], e1ap[0], ul, vl) & ((b00 & 1u) * 0xffffu + (b00 & 2u) * 0x7fff8000u);
                afA[1] = pmaxmul(e1p[1], e1ap[1], ul, vl) & ((b10 & 1u) * 0xffffu + (b10 & 2u) * 0x7fff8000u);
                afA[2] = pmaxmul(e1p[0], e1ap[0], uh, vh) & ((b01 & 1u) * 0xffffu + (b01 & 2u) * 0x7fff8000u);
                afA[3] = pmaxmul(e1p[1], e1ap[1], uh, vh) & ((b11 & 1u) * 0xffffu + (b11 & 2u) * 0x7fff8000u);
            }
            {
                uint32_t b00 = (mb2 >> (2 * tig)) & 3u;
                uint32_t b01 = (mb2 >> (2 * tig + 8)) & 3u;
                uint32_t b10 = (mb3 >> (2 * tig)) & 3u;
                uint32_t b11 = (mb3 >> (2 * tig + 8)) & 3u;
                afB[0] = pmaxmul(e1p[2], e1ap[2], ul, vl) & ((b00 & 1u) * 0xffffu + (b00 & 2u) * 0x7fff8000u);
                afB[1] = pmaxmul(e1p[3], e1ap[3], ul, vl) & ((b10 & 1u) * 0xffffu + (b10 & 2u) * 0x7fff8000u);
                afB[2] = pmaxmul(e1p[2], e1ap[2], uh, vh) & ((b01 & 1u) * 0xffffu + (b01 & 2u) * 0x7fff8000u);
                afB[3] = pmaxmul(e1p[3], e1ap[3], uh, vh) & ((b11 & 1u) * 0xffffu + (b11 & 2u) * 0x7fff8000u);
            }
            mma16816(accs, afA, ones2);
            mma16816(accs + 4, afB, ones2);
            uint32_t bk = (uint32_t)((ks >> 2) * 8192 + (ks & 3) * 32) + b_sel;
#pragma unroll
            for (int ng = 0; ng < 4; ng++) {
                uint32_t bo = SWZ(bk + (uint32_t)((ng * 16 + bnb) * 128));
                uint32_t bhf[4];
                ldsm4(bhf, smb + SM_B(b) + bo);
                mma16816(acc + ng * 8, afA, bhf);
                mma16816(acc + ng * 8 + 4, afA, bhf + 2);
                mma16816(acc + 32 + ng * 8, afB, bhf);
                mma16816(acc + 32 + ng * 8 + 4, afB, bhf + 2);
            }
        }
        CP_WAIT0();
        __syncthreads();
    }

#pragma unroll
    for (int ti = 0; ti < 2; ti++) {
        int rA = wid * 32 + ti * 16 + g, rB = rA + 8;
        float invA = 1.f / accs[ti * 4 + 0];
        float invB = 1.f / accs[ti * 4 + 2];
        float* outA = &g_hbuf[((size_t)gg * N + n0 + rA) * 256 + h * 64];
        float* outB = &g_hbuf[((size_t)gg * N + n0 + rB) * 256 + h * 64];
#pragma unroll
        for (int nt = 0; nt < 8; nt++) {
            int col = nt * 8 + 2 * tig;
            float v0 = acc[ti * 32 + nt * 4 + 0] * invA;
            float v1 = acc[ti * 32 + nt * 4 + 1] * invA;
            float v2 = acc[ti * 32 + nt * 4 + 2] * invB;
            float v3 = acc[ti * 32 + nt * 4 + 3] * invB;
            v0 = v0 > 0.f ? v0 : expm1f(v0);
            v1 = v1 > 0.f ? v1 : expm1f(v1);
            v2 = v2 > 0.f ? v2 : expm1f(v2);
            v3 = v3 > 0.f ? v3 : expm1f(v3);
            *(float2*)(outA + col) = make_float2(v0, v1);
            *(float2*)(outB + col) = make_float2(v2, v3);
        }
    }
}

// ---------------------------------------------------------------------------
// Kernel 3: head. 8 nodes/block, 256 threads, d-split pairs.
// ---------------------------------------------------------------------------
__global__ void head_kernel(const float* __restrict__ W_int, const float* __restrict__ b_int,
                            const float* __restrict__ W_fus, const float* __restrict__ b_fus,
                            float* __restrict__ out) {
    __shared__ float hs[8][776];
    __shared__ float wint_s[16][260];
    __shared__ float wfus_s[16][49];
    __shared__ float xis[8][49];
    int n0 = blockIdx.x * 8;
    int t = threadIdx.x;

    for (int i = t; i < NCLASS * 64; i += 256) {
        int c = i >> 6, dq = i & 63;
        *(float4*)&wint_s[c][dq * 4] = ((const float4*)W_int)[i];
    }
    for (int i = t; i < NCLASS * 48; i += 256) wfus_s[i / 48][i % 48] = W_fus[i];
    for (int i = t; i < 8 * 192; i += 256) {
        int nl = i / 192, rq = i % 192;
        int d4 = rq * 4, g = d4 >> 8, dd = d4 & 255;
        *(float4*)&hs[nl][d4] = *(const float4*)&g_hbuf[((size_t)g * N + n0 + nl) * 256 + dd];
    }
    __syncthreads();

    int c = t & 15, halfd = (t >> 4) & 1, nl = t >> 5;
    {
        const float4* wr = (const float4*)&wint_s[c][0];
#pragma unroll
        for (int g = 0; g < NGRAPH; g++) {
            float a0 = 0.f, a1 = 0.f, a2 = 0.f, a3 = 0.f;
            const float4* hr = (const float4*)&hs[nl][g * 256];
#pragma unroll 8
            for (int d = halfd * 32; d < halfd * 32 + 32; d++) {
                float4 hv = hr[d], wv = wr[d];
                a0 = fmaf(hv.x, wv.x, a0);
                a1 = fmaf(hv.y, wv.y, a1);
                a2 = fmaf(hv.z, wv.z, a2);
                a3 = fmaf(hv.w, wv.w, a3);
            }
            float acc = (a0 + a1) + (a2 + a3);
            acc += __shfl_xor_sync(0xffffffffu, acc, 16);
            if (halfd == 0) {
                acc += b_int[c];
                xis[nl][g * 16 + c] = acc > 0.f ? acc : expm1f(acc);
            }
        }
    }
    __syncthreads();
    if (halfd == 0) {
        float acc = b_fus[c];
        const float* wr = wfus_s[c];
        const float* xr = xis[nl];
#pragma unroll
        for (int j = 0; j < 48; j++) acc = fmaf(xr[j], wr[j], acc);
        float mx = acc;
#pragma unroll
        for (int k = 8; k; k >>= 1) mx = fmaxf(mx, __shfl_xor_sync(0xffffffffu, mx, k, 16));
        float s = expf(acc - mx);
#pragma unroll
        for (int k = 8; k; k >>= 1) s += __shfl_xor_sync(0xffffffffu, s, k, 16);
        out[(size_t)(n0 + nl) * NCLASS + c] = acc - mx - logf(s);
    }
}

// ---------------------------------------------------------------------------
// Kernel 4: l1_loss = mean(|W_fus|)
// ---------------------------------------------------------------------------
__global__ void l1_kernel(const float* __restrict__ W_fus, float* __restrict__ out) {
    __shared__ float red[256];
    int t = threadIdx.x;
    float s = 0.f;
    for (int i = t; i < NCLASS * NGRAPH * NCLASS; i += 256) s += fabsf(W_fus[i]);
    red[t] = s;
    __syncthreads();
    for (int k = 128; k; k >>= 1) {
        if (t < k) red[t] += red[t + k];
        __syncthreads();
    }
    if (t == 0) out[(size_t)N * NCLASS] = red[0] / (float)(NCLASS * NGRAPH * NCLASS);
}

// ---------------------------------------------------------------------------
extern "C" void kernel_launch(void* const* d_in, const int* in_sizes, int n_in,
                              void* d_out, int out_size) {
    const float* x     = (const float*)d_in[0];
    const int*   adj   = (const int*)d_in[1];
    const float* W     = (const float*)d_in[2];
    const float* a     = (const float*)d_in[3];
    const float* W_int = (const float*)d_in[4];
    const float* b_int = (const float*)d_in[5];
    const float* W_fus = (const float*)d_in[6];
    const float* b_fus = (const float*)d_in[7];
    float* out = (float*)d_out;

    cudaFuncSetAttribute(wh_mma_kernel, cudaFuncAttributeMaxDynamicSharedMemorySize, WH_SMEM);
    cudaFuncSetAttribute(attn_mma_kernel, cudaFuncAttributeMaxDynamicSharedMemorySize, ATTN_SMEM);

    // Fork: adjpack (+l1) on a side stream, overlapped with prep+wh_mma.
    // Streams/events created per call and intentionally leaked (few calls ever;
    // replays reuse the captured graph).
    cudaStream_t s2;
    cudaStreamCreateWithFlags(&s2, cudaStreamNonBlocking);
    cudaEvent_t evF, evJ;
    cudaEventCreateWithFlags(&evF, cudaEventDisableTiming);
    cudaEventCreateWithFlags(&evJ, cudaEventDisableTiming);

    cudaEventRecord(evF, 0);
    cudaStreamWaitEvent(s2, evF, 0);
    adjpack_kernel<<<(NGRAPH * N * N) / (8 * 1024), 256, 0, s2>>>(adj);
    if (out_size > N * NCLASS) l1_kernel<<<1, 256, 0, s2>>>(W_fus, out);

    prep_kernel<<<1632, 256>>>(x, W);
    wh_mma_kernel<<<dim3(N / 128, NGRAPH * NHEADS), 256, WH_SMEM>>>(a);

    cudaEventRecord(evJ, s2);
    cudaStreamWaitEvent(0, evJ, 0);
    attn_mma_kernel<<<dim3(N / 256, NGRAPH * NHEADS), 256, ATTN_SMEM>>>();
    head_kernel<<<N / 8, 256>>>(W_int, b_int, W_fus, b_fus, out);
}

// round 17
// speedup vs baseline: 1.2237x; 1.0510x over previous
#include <cuda_runtime.h>
#include <cuda_bf16.h>
#include <math.h>
#include <stdint.h>

#define N 3072
#define F_IN 512
#define NHID 64
#define NHEADS 4
#define NGRAPH 3
#define NCLASS 16
#define ALPHA 0.2f

// ---------------- scratch globals (no allocation) ----------------
__device__ float2 g_E1[NGRAPH * NHEADS * N];                  // {exp(f1), exp(a*f1)}
__device__ __nv_bfloat16 g_E2b[NGRAPH * NHEADS * N];          // bf16(exp(f2))
__device__ __nv_bfloat16 g_E2ab[NGRAPH * NHEADS * N];         // bf16(exp(a*f2))
__device__ __nv_bfloat16 g_WhTh[NGRAPH * NHEADS * NHID * N];  // [gh][o][m] (attn B)
__device__ __nv_bfloat16 g_xh[N * F_IN];                      // x bf16 hi
__device__ __nv_bfloat16 g_WTh[NGRAPH * NHEADS * NHID * F_IN];// W^T [gh][o][f] hi
__device__ __nv_bfloat16 g_WTl[NGRAPH * NHEADS * NHID * F_IN];// W^T lo
__device__ uint32_t g_adjbits[NGRAPH * N * (N / 32)];         // adj bitmask
__device__ float g_hbuf[NGRAPH * N * NHEADS * NHID];          // [g][n][h*64+o]

// ---------------- helpers ----------------
__device__ __forceinline__ uint32_t smem_u32(const void* p) {
    uint32_t a;
    asm("{ .reg .u64 t; cvta.to.shared.u64 t, %1; cvt.u32.u64 %0, t; }" : "=r"(a) : "l"(p));
    return a;
}
__device__ __forceinline__ uint32_t bf16pack(float lo, float hi) {
    uint32_t r;
    asm("cvt.rn.satfinite.bf16x2.f32 %0, %1, %2;" : "=r"(r) : "f"(hi), "f"(lo));
    return r;  // low 16 bits = lo-arg
}
__device__ __forceinline__ void ldsm4(uint32_t* r, uint32_t addr) {
    asm volatile("ldmatrix.sync.aligned.m8n8.x4.shared.b16 {%0,%1,%2,%3}, [%4];"
                 : "=r"(r[0]), "=r"(r[1]), "=r"(r[2]), "=r"(r[3]) : "r"(addr));
}
__device__ __forceinline__ void mma16816(float* c, const uint32_t* a, const uint32_t* b) {
    asm volatile("mma.sync.aligned.m16n8k16.row.col.f32.bf16.bf16.f32 "
                 "{%0,%1,%2,%3}, {%4,%5,%6,%7}, {%8,%9}, {%0,%1,%2,%3};"
                 : "+f"(c[0]), "+f"(c[1]), "+f"(c[2]), "+f"(c[3])
                 : "r"(a[0]), "r"(a[1]), "r"(a[2]), "r"(a[3]), "r"(b[0]), "r"(b[1]));
}
__device__ __forceinline__ uint32_t pmaxmul(uint32_t e1p, uint32_t e1ap, uint32_t u, uint32_t v) {
    uint32_t r;
    asm("{ .reg .b32 t1, t2;\n\t"
        "mul.bf16x2 t1, %1, %3;\n\t"
        "mul.bf16x2 t2, %2, %4;\n\t"
        "max.bf16x2 %0, t1, t2; }"
        : "=r"(r) : "r"(e1p), "r"(e1ap), "r"(u), "r"(v));
    return r;
}
__device__ __forceinline__ void cpasync16(uint32_t saddr, const void* gptr) {
    asm volatile("cp.async.cg.shared.global [%0], [%1], 16;" :: "r"(saddr), "l"(gptr) : "memory");
}
__device__ __forceinline__ void cpasync8(uint32_t saddr, const void* gptr) {
    asm volatile("cp.async.ca.shared.global [%0], [%1], 8;" :: "r"(saddr), "l"(gptr) : "memory");
}
#define CP_COMMIT() asm volatile("cp.async.commit_group;" ::: "memory")
#define CP_WAIT0()  asm volatile("cp.async.wait_group 0;" ::: "memory")
#define CP_WAIT1()  asm volatile("cp.async.wait_group 1;" ::: "memory")
#define SWZ(x) ((x) ^ ((((uint32_t)(x)) >> 3) & 0x70))

// ---------------------------------------------------------------------------
// Prep (merged): blocks [0,1536): x -> bf16 hi. Blocks [1536,1632): W^T split.
// ---------------------------------------------------------------------------
__global__ void prep_kernel(const float* __restrict__ x, const float* __restrict__ W) {
    int bx = blockIdx.x;
    int t = threadIdx.x;
    if (bx < 1536) {
        int idx = bx * 256 + t;
        float4 v = ((const float4*)x)[idx];
        uint32_t h0 = bf16pack(v.x, v.y), h1 = bf16pack(v.z, v.w);
        *(uint2*)&g_xh[(size_t)idx * 4] = make_uint2(h0, h1);
    } else {
        __shared__ float tile[64][65];
        int b2 = bx - 1536;
        int gh = b2 >> 3, f0 = (b2 & 7) * 64;
        const float* Wgh = W + (size_t)gh * F_IN * NHID + (size_t)f0 * NHID;
#pragma unroll
        for (int i = 0; i < 16; i++) {
            int idx = t + 256 * i;
            tile[idx >> 6][idx & 63] = Wgh[idx];
        }
        __syncthreads();
        int o = t >> 2, fq = t & 3;
        size_t base = ((size_t)gh * 64 + o) * F_IN + f0 + fq * 16;
#pragma unroll
        for (int j = 0; j < 8; j++) {
            int f = fq * 16 + 2 * j;
            float w0 = tile[f][o], w1 = tile[f + 1][o];
            uint32_t hv = bf16pack(w0, w1);
            float l0 = w0 - __uint_as_float(hv << 16);
            float l1 = w1 - __uint_as_float(hv & 0xffff0000u);
            *(uint32_t*)&g_WTh[base + 2 * j] = hv;
            *(uint32_t*)&g_WTl[base + 2 * j] = bf16pack(l0, l1);
        }
    }
}

// ---------------------------------------------------------------------------
// Prep: adj -> bitmask via ballot.
// ---------------------------------------------------------------------------
__global__ void adjpack_kernel(const int* __restrict__ adj) {
    int lane = threadIdx.x & 31;
    size_t wid = ((size_t)blockIdx.x * 256 + threadIdx.x) >> 5;
    size_t base = wid * 1024;
    uint32_t myw = 0;
#pragma unroll
    for (int i = 0; i < 32; i++) {
        int v = adj[base + i * 32 + lane];
        uint32_t b = __ballot_sync(0xffffffffu, v > 0);
        if (lane == i) myw = b;
    }
    g_adjbits[base / 32 + lane] = myw;
}

// ---------------------------------------------------------------------------
// Kernel 1: Wh = x@W (mma.sync, 2-term, double-buffered cp.async pipeline).
// Epilogue: WhT bf16 + f1/f2 -> E1/E2.
// ---------------------------------------------------------------------------
#define WH_BUF 32768
#define WH_SMEM 66048
extern __shared__ char whsm[];
__global__ __launch_bounds__(256, 2) void wh_mma_kernel(const float* __restrict__ a) {
    char* sm = whsm;
    uint32_t smb = smem_u32(sm);
    float* a_s = (float*)(sm + 65536);
    int t = threadIdx.x;
    int wid = t >> 5, lane = t & 31;
    int gh = blockIdx.y;
    int n0 = blockIdx.x * 128;

    if (t < 128) a_s[t] = a[gh * 128 + t];

    int lrow = lane & 7, seg = lane >> 3;
    int arow = wid * 16 + lrow + (seg & 1) * 8;
    uint32_t a_sel = (uint32_t)((seg >> 1) * 16);
    int bnb = lrow + (seg >> 1) * 8;
    uint32_t b_sel = (uint32_t)((seg & 1) * 16);

    int rowA = t >> 1, halfA = t & 1;
    int ob = t >> 2, qb = t & 3;

    float acc[32];
#pragma unroll
    for (int i = 0; i < 32; i++) acc[i] = 0.f;

    auto stage = [&](int f0, int b) {
        uint32_t bb = (uint32_t)b * WH_BUF;
        const char* sh = (const char*)&g_xh[(size_t)(n0 + rowA) * F_IN + f0 + halfA * 32];
#pragma unroll
        for (int j = 0; j < 4; j++) {
            uint32_t s = SWZ((uint32_t)(rowA * 128 + halfA * 64 + j * 16)) + bb;
            cpasync16(smb + s, sh + j * 16);
        }
        const char* th = (const char*)&g_WTh[((size_t)gh * 64 + ob) * F_IN + f0 + qb * 16];
        const char* tl = (const char*)&g_WTl[((size_t)gh * 64 + ob) * F_IN + f0 + qb * 16];
#pragma unroll
        for (int j = 0; j < 2; j++) {
            uint32_t s = SWZ((uint32_t)(ob * 128 + qb * 32 + j * 16)) + bb;
            cpasync16(smb + 16384 + s, th + j * 16);
            cpasync16(smb + 24576 + s, tl + j * 16);
        }
    };

    stage(0, 0);
    CP_COMMIT();
    CP_WAIT0();
    __syncthreads();
    for (int ci = 0; ci < 8; ci++) {
        int b = ci & 1;
        if (ci < 7) { stage((ci + 1) * 64, b ^ 1); CP_COMMIT(); }
        uint32_t bb = (uint32_t)b * WH_BUF;
#pragma unroll
        for (int ks = 0; ks < 4; ks++) {
            uint32_t ao = SWZ((uint32_t)(arow * 128 + ks * 32) + a_sel) + bb;
            uint32_t ah[4];
            ldsm4(ah, smb + ao);
#pragma unroll
            for (int ng = 0; ng < 4; ng++) {
                uint32_t bo = SWZ((uint32_t)((ng * 16 + bnb) * 128 + ks * 32) + b_sel) + bb;
                uint32_t bh[4], bl[4];
                ldsm4(bh, smb + 16384 + bo);
                ldsm4(bl, smb + 24576 + bo);
                mma16816(acc + ng * 8, ah, bh);
                mma16816(acc + ng * 8 + 4, ah, bh + 2);
                mma16816(acc + ng * 8, ah, bl);
                mma16816(acc + ng * 8 + 4, ah, bl + 2);
            }
        }
        CP_WAIT0();
        __syncthreads();
    }

    int gID = lane >> 2, tig = lane & 3;
    int rA = wid * 16 + gID, rB = rA + 8;
    float* ftile = (float*)sm;  // [128][66]
#pragma unroll
    for (int ng = 0; ng < 4; ng++) {
        int col = ng * 16 + 2 * tig;
        ftile[rA * 66 + col] = acc[ng * 8 + 0];
        ftile[rA * 66 + col + 1] = acc[ng * 8 + 1];
        ftile[rB * 66 + col] = acc[ng * 8 + 2];
        ftile[rB * 66 + col + 1] = acc[ng * 8 + 3];
        ftile[rA * 66 + col + 8] = acc[ng * 8 + 4];
        ftile[rA * 66 + col + 9] = acc[ng * 8 + 5];
        ftile[rB * 66 + col + 8] = acc[ng * 8 + 6];
        ftile[rB * 66 + col + 9] = acc[ng * 8 + 7];
    }
    __syncthreads();
    {
        int o = t >> 2, rq = t & 3;
        size_t base = ((size_t)gh * 64 + o) * N + n0 + rq * 32;
#pragma unroll
        for (int j = 0; j < 16; j++) {
            int r = rq * 32 + 2 * j;
            *(uint32_t*)&g_WhTh[base + 2 * j] = bf16pack(ftile[r * 66 + o], ftile[(r + 1) * 66 + o]);
        }
    }
    {
        int row = t >> 1, halfo = t & 1;
        const float* fr = ftile + row * 66 + halfo * 32;
        const float* a1 = a_s + halfo * 32;
        const float* a2 = a_s + 64 + halfo * 32;
        float s1 = 0.f, s2 = 0.f;
#pragma unroll 8
        for (int o = 0; o < 32; o++) {
            float w = fr[o];
            s1 = fmaf(w, a1[o], s1);
            s2 = fmaf(w, a2[o], s2);
        }
        s1 += __shfl_xor_sync(0xffffffffu, s1, 1);
        s2 += __shfl_xor_sync(0xffffffffu, s2, 1);
        if (halfo == 0) {
            int n = n0 + row;
            g_E1[gh * N + n] = make_float2(__expf(s1), __expf(ALPHA * s1));
            g_E2b[gh * N + n] = __float2bfloat16(__expf(s2));
            g_E2ab[gh * N + n] = __float2bfloat16(__expf(ALPHA * s2));
        }
    }
}

// ---------------------------------------------------------------------------
// Kernel 2: attention. Round-10 decomposition (256 thr, 32 rows/warp) with:
//  - triple-buffered cp.async staging, prefetch distance 2 (wait_group 1)
//  - adj-bits prefetched one chunk ahead into registers.
// smem: B 3x16K + e2 3x1K = 52224
// ---------------------------------------------------------------------------
#define SM_B(b)   ((b) * 16384)
#define SM_E2(b)  (49152 + (b) * 1024)
#define SM_E2A(b) (49152 + (b) * 1024 + 256)
#define ATTN_SMEM 52224
extern __shared__ char attn_sm[];
__global__ __launch_bounds__(256, 1) void attn_mma_kernel() {
    char* sm = attn_sm;
    uint32_t smb = smem_u32(sm);
    int t = threadIdx.x;
    int wid = t >> 5, lane = t & 31;
    int gh = blockIdx.y, gg = gh >> 2, h = gh & 3;
    int n0 = blockIdx.x * 256;
    int g = lane >> 2, tig = lane & 3;

    uint32_t e1p[4], e1ap[4];
#pragma unroll
    for (int i = 0; i < 4; i++) {
        float2 E1v = g_E1[gh * N + n0 + wid * 32 + i * 8 + g];
        e1p[i] = bf16pack(E1v.x, E1v.x);
        e1ap[i] = bf16pack(E1v.y, E1v.y);
    }
    const uint4* bits0 = (const uint4*)(g_adjbits + ((size_t)gg * N + n0 + wid * 32 + g) * 96);
    const uint4* bits1 = (const uint4*)(g_adjbits + ((size_t)gg * N + n0 + wid * 32 + 8 + g) * 96);
    const uint4* bits2 = (const uint4*)(g_adjbits + ((size_t)gg * N + n0 + wid * 32 + 16 + g) * 96);
    const uint4* bits3 = (const uint4*)(g_adjbits + ((size_t)gg * N + n0 + wid * 32 + 24 + g) * 96);

    int ob = t >> 2, mq = t & 3;
    const __nv_bfloat16* bh_row = g_WhTh + ((size_t)gh * 64 + ob) * N + mq * 32;
    uint32_t b_off_base = (uint32_t)((mq >> 1) * 8192 + ob * 128 + (mq & 1) * 64);
    const uint2* e2src = (const uint2*)(g_E2b + (size_t)gh * N);
    const uint2* e2asrc = (const uint2*)(g_E2ab + (size_t)gh * N);

    int lrow = lane & 7, seg = lane >> 3;
    int bnb = lrow + (seg >> 1) * 8;
    uint32_t b_sel = (uint32_t)((seg & 1) * 16);

    const uint32_t ones2[2] = {0x3F803F80u, 0x3F803F80u};
    float acc[64], accs[8];
#pragma unroll
    for (int i = 0; i < 64; i++) acc[i] = 0.f;
#pragma unroll
    for (int i = 0; i < 8; i++) accs[i] = 0.f;

    auto stage = [&](int c, int b) {
        const char* hs = (const char*)(bh_row + c * 128);
#pragma unroll
        for (int jj = 0; jj < 4; jj++)
            cpasync16(smb + SM_B(b) + SWZ(b_off_base + jj * 16), hs + jj * 16);
        if (t < 32) cpasync8(smb + SM_E2(b) + t * 8, (const char*)(e2src + c * 32 + t));
        else if (t < 64) cpasync8(smb + SM_E2A(b) + (t - 32) * 8, (const char*)(e2asrc + c * 32 + (t - 32)));
    };

    // prime: stage chunks 0 and 1; prefetch bits for chunk 0
    stage(0, 0); CP_COMMIT();
    stage(1, 1); CP_COMMIT();
    uint4 w0 = bits0[0], w1 = bits1[0], w2 = bits2[0], w3 = bits3[0];
    CP_WAIT1();           // group(0) complete; group(1) may be in flight
    __syncthreads();

    for (int c = 0; c < 24; c++) {
        int b = c % 3;
        // prefetch adj bits for next chunk (latency covered by this chunk)
        uint4 nw0, nw1, nw2, nw3;
        if (c < 23) {
            nw0 = bits0[c + 1]; nw1 = bits1[c + 1];
            nw2 = bits2[c + 1]; nw3 = bits3[c + 1];
        }
        const uint32_t* e2s = (const uint32_t*)(sm + SM_E2(b));
        const uint32_t* e2as = (const uint32_t*)(sm + SM_E2A(b));
#pragma unroll
        for (int ks = 0; ks < 8; ks++) {
            uint32_t ul = e2s[ks * 8 + tig], uh = e2s[ks * 8 + 4 + tig];
            uint32_t vl = e2as[ks * 8 + tig], vh = e2as[ks * 8 + 4 + tig];
            uint32_t mb0 = ((const uint32_t*)&w0)[ks >> 1] >> ((ks & 1) * 16);
            uint32_t mb1 = ((const uint32_t*)&w1)[ks >> 1] >> ((ks & 1) * 16);
            uint32_t mb2 = ((const uint32_t*)&w2)[ks >> 1] >> ((ks & 1) * 16);
            uint32_t mb3 = ((const uint32_t*)&w3)[ks >> 1] >> ((ks & 1) * 16);
            uint32_t afA[4], afB[4];
            {
                uint32_t b00 = (mb0 >> (2 * tig)) & 3u;
                uint32_t b01 = (mb0 >> (2 * tig + 8)) & 3u;
                uint32_t b10 = (mb1 >> (2 * tig)) & 3u;
                uint32_t b11 = (mb1 >> (2 * tig + 8)) & 3u;
                afA[0] = pmaxmul(e1p[0], e1ap[0], ul, vl) & ((b00 & 1u) * 0xffffu + (b00 & 2u) * 0x7fff8000u);
                afA[1] = pmaxmul(e1p[1], e1ap[1], ul, vl) & ((b10 & 1u) * 0xffffu + (b10 & 2u) * 0x7fff8000u);
                afA[2] = pmaxmul(e1p[0], e1ap[0], uh, vh) & ((b01 & 1u) * 0xffffu + (b01 & 2u) * 0x7fff8000u);
                afA[3] = pmaxmul(e1p[1], e1ap[1], uh, vh) & ((b11 & 1u) * 0xffffu + (b11 & 2u) * 0x7fff8000u);
            }
            {
                uint32_t b00 = (mb2 >> (2 * tig)) & 3u;
                uint32_t b01 = (mb2 >> (2 * tig + 8)) & 3u;
                uint32_t b10 = (mb3 >> (2 * tig)) & 3u;
                uint32_t b11 = (mb3 >> (2 * tig + 8)) & 3u;
                afB[0] = pmaxmul(e1p[2], e1ap[2], ul, vl) & ((b00 & 1u) * 0xffffu + (b00 & 2u) * 0x7fff8000u);
                afB[1] = pmaxmul(e1p[3], e1ap[3], ul, vl) & ((b10 & 1u) * 0xffffu + (b10 & 2u) * 0x7fff8000u);
                afB[2] = pmaxmul(e1p[2], e1ap[2], uh, vh) & ((b01 & 1u) * 0xffffu + (b01 & 2u) * 0x7fff8000u);
                afB[3] = pmaxmul(e1p[3], e1ap[3], uh, vh) & ((b11 & 1u) * 0xffffu + (b11 & 2u) * 0x7fff8000u);
            }
            mma16816(accs, afA, ones2);
            mma16816(accs + 4, afB, ones2);
            uint32_t bk = (uint32_t)((ks >> 2) * 8192 + (ks & 3) * 32) + b_sel;
#pragma unroll
            for (int ng = 0; ng < 4; ng++) {
                uint32_t bo = SWZ(bk + (uint32_t)((ng * 16 + bnb) * 128));
                uint32_t bhf[4];
                ldsm4(bhf, smb + SM_B(b) + bo);
                mma16816(acc + ng * 8, afA, bhf);
                mma16816(acc + ng * 8 + 4, afA, bhf + 2);
                mma16816(acc + 32 + ng * 8, afB, bhf);
                mma16816(acc + 32 + ng * 8 + 4, afB, bhf + 2);
            }
        }
        if (c < 22) {
            stage(c + 2, (c + 2) % 3);
            CP_COMMIT();
            CP_WAIT1();   // group(c+1) complete; group(c+2) may be pending
        } else {
            CP_WAIT0();
        }
        w0 = nw0; w1 = nw1; w2 = nw2; w3 = nw3;
        __syncthreads();
    }

#pragma unroll
    for (int ti = 0; ti < 2; ti++) {
        int rA = wid * 32 + ti * 16 + g, rB = rA + 8;
        float invA = 1.f / accs[ti * 4 + 0];
        float invB = 1.f / accs[ti * 4 + 2];
        float* outA = &g_hbuf[((size_t)gg * N + n0 + rA) * 256 + h * 64];
        float* outB = &g_hbuf[((size_t)gg * N + n0 + rB) * 256 + h * 64];
#pragma unroll
        for (int nt = 0; nt < 8; nt++) {
            int col = nt * 8 + 2 * tig;
            float v0 = acc[ti * 32 + nt * 4 + 0] * invA;
            float v1 = acc[ti * 32 + nt * 4 + 1] * invA;
            float v2 = acc[ti * 32 + nt * 4 + 2] * invB;
            float v3 = acc[ti * 32 + nt * 4 + 3] * invB;
            v0 = v0 > 0.f ? v0 : expm1f(v0);
            v1 = v1 > 0.f ? v1 : expm1f(v1);
            v2 = v2 > 0.f ? v2 : expm1f(v2);
            v3 = v3 > 0.f ? v3 : expm1f(v3);
            *(float2*)(outA + col) = make_float2(v0, v1);
            *(float2*)(outB + col) = make_float2(v2, v3);
        }
    }
}

// ---------------------------------------------------------------------------
// Kernel 3: head. 8 nodes/block, 256 threads, d-split pairs.
// ---------------------------------------------------------------------------
__global__ void head_kernel(const float* __restrict__ W_int, const float* __restrict__ b_int,
                            const float* __restrict__ W_fus, const float* __restrict__ b_fus,
                            float* __restrict__ out) {
    __shared__ float hs[8][776];
    __shared__ float wint_s[16][260];
    __shared__ float wfus_s[16][49];
    __shared__ float xis[8][49];
    int n0 = blockIdx.x * 8;
    int t = threadIdx.x;

    for (int i = t; i < NCLASS * 64; i += 256) {
        int c = i >> 6, dq = i & 63;
        *(float4*)&wint_s[c][dq * 4] = ((const float4*)W_int)[i];
    }
    for (int i = t; i < NCLASS * 48; i += 256) wfus_s[i / 48][i % 48] = W_fus[i];
    for (int i = t; i < 8 * 192; i += 256) {
        int nl = i / 192, rq = i % 192;
        int d4 = rq * 4, g = d4 >> 8, dd = d4 & 255;
        *(float4*)&hs[nl][d4] = *(const float4*)&g_hbuf[((size_t)g * N + n0 + nl) * 256 + dd];
    }
    __syncthreads();

    int c = t & 15, halfd = (t >> 4) & 1, nl = t >> 5;
    {
        const float4* wr = (const float4*)&wint_s[c][0];
#pragma unroll
        for (int g = 0; g < NGRAPH; g++) {
            float a0 = 0.f, a1 = 0.f, a2 = 0.f, a3 = 0.f;
            const float4* hr = (const float4*)&hs[nl][g * 256];
#pragma unroll 8
            for (int d = halfd * 32; d < halfd * 32 + 32; d++) {
                float4 hv = hr[d], wv = wr[d];
                a0 = fmaf(hv.x, wv.x, a0);
                a1 = fmaf(hv.y, wv.y, a1);
                a2 = fmaf(hv.z, wv.z, a2);
                a3 = fmaf(hv.w, wv.w, a3);
            }
            float acc = (a0 + a1) + (a2 + a3);
            acc += __shfl_xor_sync(0xffffffffu, acc, 16);
            if (halfd == 0) {
                acc += b_int[c];
                xis[nl][g * 16 + c] = acc > 0.f ? acc : expm1f(acc);
            }
        }
    }
    __syncthreads();
    if (halfd == 0) {
        float acc = b_fus[c];
        const float* wr = wfus_s[c];
        const float* xr = xis[nl];
#pragma unroll
        for (int j = 0; j < 48; j++) acc = fmaf(xr[j], wr[j], acc);
        float mx = acc;
#pragma unroll
        for (int k = 8; k; k >>= 1) mx = fmaxf(mx, __shfl_xor_sync(0xffffffffu, mx, k, 16));
        float s = expf(acc - mx);
#pragma unroll
        for (int k = 8; k; k >>= 1) s += __shfl_xor_sync(0xffffffffu, s, k, 16);
        out[(size_t)(n0 + nl) * NCLASS + c] = acc - mx - logf(s);
    }
}

// ---------------------------------------------------------------------------
// Kernel 4: l1_loss = mean(|W_fus|)
// ---------------------------------------------------------------------------
__global__ void l1_kernel(const float* __restrict__ W_fus, float* __restrict__ out) {
    __shared__ float red[256];
    int t = threadIdx.x;
    float s = 0.f;
    for (int i = t; i < NCLASS * NGRAPH * NCLASS; i += 256) s += fabsf(W_fus[i]);
    red[t] = s;
    __syncthreads();
    for (int k = 128; k; k >>= 1) {
        if (t < k) red[t] += red[t + k];
        __syncthreads();
    }
    if (t == 0) out[(size_t)N * NCLASS] = red[0] / (float)(NCLASS * NGRAPH * NCLASS);
}

// ---------------------------------------------------------------------------
extern "C" void kernel_launch(void* const* d_in, const int* in_sizes, int n_in,
                              void* d_out, int out_size) {
    const float* x     = (const float*)d_in[0];
    const int*   adj   = (const int*)d_in[1];
    const float* W     = (const float*)d_in[2];
    const float* a     = (const float*)d_in[3];
    const float* W_int = (const float*)d_in[4];
    const float* b_int = (const float*)d_in[5];
    const float* W_fus = (const float*)d_in[6];
    const float* b_fus = (const float*)d_in[7];
    float* out = (float*)d_out;

    cudaFuncSetAttribute(wh_mma_kernel, cudaFuncAttributeMaxDynamicSharedMemorySize, WH_SMEM);
    cudaFuncSetAttribute(attn_mma_kernel, cudaFuncAttributeMaxDynamicSharedMemorySize, ATTN_SMEM);

    // Fork: adjpack (+l1) on a side stream, overlapped with prep+wh_mma.
    // Streams/events created per call and intentionally leaked (few calls ever;
    // replays reuse the captured graph).
    cudaStream_t s2;
    cudaStreamCreateWithFlags(&s2, cudaStreamNonBlocking);
    cudaEvent_t evF, evJ;
    cudaEventCreateWithFlags(&evF, cudaEventDisableTiming);
    cudaEventCreateWithFlags(&evJ, cudaEventDisableTiming);

    cudaEventRecord(evF, 0);
    cudaStreamWaitEvent(s2, evF, 0);
    adjpack_kernel<<<(NGRAPH * N * N) / (8 * 1024), 256, 0, s2>>>(adj);
    if (out_size > N * NCLASS) l1_kernel<<<1, 256, 0, s2>>>(W_fus, out);

    prep_kernel<<<1632, 256>>>(x, W);
    wh_mma_kernel<<<dim3(N / 128, NGRAPH * NHEADS), 256, WH_SMEM>>>(a);

    cudaEventRecord(evJ, s2);
    cudaStreamWaitEvent(0, evJ, 0);
    attn_mma_kernel<<<dim3(N / 256, NGRAPH * NHEADS), 256, ATTN_SMEM>>>();
    head_kernel<<<N / 8, 256>>>(W_int, b_int, W_fus, b_fus, out);
}